// round 13
// baseline (speedup 1.0000x reference)
#include <cuda_runtime.h>
#include <cuda_fp16.h>

#define N_USERS 100000
#define N_ITEMS 200000
#define N_NODESC 300000
#define EMB 64
#define NLAYERS 3
#define N_EDGESC 9600000
#define BATCHC 4096
#define NEG_SLOPE 0.2f

#define TN 64
#define TTHREADS 256
#define SPX_STRIDE 66   // ull per node row (64 + 2 pad)
#define WCH_STRIDE 514  // ull per weight chunk (512 + 2 pad)
#define ELLW 128        // ELL slots per node; P(Poisson(32) >= 128) ~ 1e-35

// ---------------- device scratch (no mallocs allowed) ----------------
__device__ float g_ego[N_NODESC * EMB];
__device__ uint2 g_egoH[N_NODESC * 16];
__device__ float g_neigh[N_NODESC * EMB];
__device__ int   g_cursor[N_NODESC];            // degree counter / scatter cursor
__device__ int2  g_cedge[N_NODESC * ELLW];      // ELL (col, val-bits)
// frontier machinery
__device__ int   g_flag2[N_NODESC];
__device__ int   g_flag3[N_NODESC];
__device__ int   g_list2[N_NODESC];
__device__ int   g_list3[3 * BATCHC];
__device__ int   g_nf2;
__device__ int   g_nf3;

// ---------------- f32x2 helpers ----------------
__device__ __forceinline__ void fma2(unsigned long long& d, unsigned long long a,
                                     unsigned long long b) {
    asm("fma.rn.f32x2 %0, %1, %2, %0;" : "+l"(d) : "l"(a), "l"(b));
}
__device__ __forceinline__ unsigned long long pk2(float lo, float hi) {
    unsigned long long r;
    asm("mov.b64 %0, {%1, %2};" : "=l"(r) : "f"(lo), "f"(hi));
    return r;
}
__device__ __forceinline__ float2 upk2(unsigned long long v) {
    float lo, hi;
    asm("mov.b64 {%0, %1}, %2;" : "=f"(lo), "=f"(hi) : "l"(v));
    return make_float2(lo, hi);
}

// ---------------- kernel 1: prep = zero + copy_ego + stage-0 output ----------------
__global__ void prep_kernel(const float4* __restrict__ ue,
                            const float4* __restrict__ ie,
                            const int* __restrict__ users,
                            const int* __restrict__ pos,
                            const int* __restrict__ neg,
                            float* __restrict__ out) {
    int gid = blockIdx.x * blockDim.x + threadIdx.x;   // 0 .. 4.8M-1

    // zero cursors/flags
    if (gid < N_NODESC) {
        g_cursor[gid] = 0;
        g_flag2[gid] = 0;
        g_flag3[gid] = 0;
    }
    if (gid == 0) { g_nf2 = 0; g_nf3 = 0; }

    // copy ego (fp32 + fp16 mirror)
    {
        float4* ego4 = reinterpret_cast<float4*>(g_ego);
        const int ucount = N_USERS * (EMB / 4);
        float4 v = (gid < ucount) ? ue[gid] : ie[gid - ucount];
        ego4[gid] = v;
        __half2 h0 = __float22half2_rn(make_float2(v.x, v.y));
        __half2 h1 = __float22half2_rn(make_float2(v.z, v.w));
        uint2 p;
        p.x = *reinterpret_cast<unsigned*>(&h0);
        p.y = *reinterpret_cast<unsigned*>(&h1);
        g_egoH[gid] = p;
    }

    // stage-0 output straight from source embeddings
    if (gid < 3 * BATCHC * 16) {
        int r = gid >> 4;
        int g = gid & 15;
        float4 v;
        if (r < BATCHC) {
            v = ue[users[r] * 16 + g];
        } else if (r < 2 * BATCHC) {
            v = ie[pos[r - BATCHC] * 16 + g];
        } else {
            v = ie[neg[r - 2 * BATCHC] * 16 + g];
        }
        *reinterpret_cast<float4*>(&out[(size_t)r * (4 * EMB) + g * 4]) = v;
    }
}

// ---------------- kernel 2: ELL scatter + mark3 ----------------
__global__ void scatter_kernel(const int* __restrict__ row,
                               const int* __restrict__ col,
                               const float* __restrict__ val,
                               const int* __restrict__ users,
                               const int* __restrict__ pos,
                               const int* __restrict__ neg) {
    int e = blockIdx.x * blockDim.x + threadIdx.x;
    if (e >= N_EDGESC) return;
    int r = row[e];
    int p = atomicAdd(&g_cursor[r], 1);
    if (p < ELLW)
        g_cedge[r * ELLW + p] = make_int2(col[e], __float_as_int(val[e]));

    // mark frontier-3 (batch nodes, dedup) and seed frontier-2
    if (e < 3 * BATCHC) {
        int n;
        if (e < BATCHC) n = users[e];
        else if (e < 2 * BATCHC) n = N_USERS + pos[e - BATCHC];
        else n = N_USERS + neg[e - 2 * BATCHC];
        if (atomicExch(&g_flag3[n], 1) == 0) {
            int q = atomicAdd(&g_nf3, 1);
            g_list3[q] = n;
        }
        if (atomicExch(&g_flag2[n], 1) == 0) {
            int q = atomicAdd(&g_nf2, 1);
            g_list2[q] = n;
        }
    }
}

// ---------------- kernel 3: aggregation, 8 lanes/node (uint4 gathers) ----------------
// mode 0: all nodes; mode 2: g_list2; mode 3: g_list3
__global__ void aggregate_kernel(int mode) {
    int gid = blockIdx.x * blockDim.x + threadIdx.x;
    int i = gid >> 3;
    int g = gid & 7;
    int node;
    if (mode == 0) {
        node = i;
        if (node >= N_NODESC) return;
    } else if (mode == 2) {
        if (i >= g_nf2) return;
        node = g_list2[i];
    } else {
        if (i >= g_nf3) return;
        node = g_list3[i];
    }
    const uint4* egoH4 = reinterpret_cast<const uint4*>(g_egoH);

    int cnt = min(g_cursor[node], ELLW);
    int beg = node * ELLW;
    int end = beg + cnt;
    float a0 = 0.f, a1 = 0.f, a2 = 0.f, a3 = 0.f;
    float a4 = 0.f, a5 = 0.f, a6 = 0.f, a7 = 0.f;
#pragma unroll 4
    for (int e = beg; e < end; e++) {
        int2 ev = g_cedge[e];
        float v = __int_as_float(ev.y);
        uint4 p = egoH4[ev.x * 8 + g];
        float2 f0 = __half22float2(*reinterpret_cast<__half2*>(&p.x));
        float2 f1 = __half22float2(*reinterpret_cast<__half2*>(&p.y));
        float2 f2 = __half22float2(*reinterpret_cast<__half2*>(&p.z));
        float2 f3 = __half22float2(*reinterpret_cast<__half2*>(&p.w));
        a0 += v * f0.x; a1 += v * f0.y;
        a2 += v * f1.x; a3 += v * f1.y;
        a4 += v * f2.x; a5 += v * f2.y;
        a6 += v * f3.x; a7 += v * f3.y;
    }
    float* nr = g_neigh + node * EMB + g * 8;
    *reinterpret_cast<float4*>(nr)     = make_float4(a0, a1, a2, a3);
    *reinterpret_cast<float4*>(nr + 4) = make_float4(a4, a5, a6, a7);
}

// ---------------- frontier propagate: F2 += cols of rows in F3 ----------------
__global__ void propagate_kernel() {
    int gid = blockIdx.x * blockDim.x + threadIdx.x;
    int i = gid >> 4;
    int lane = gid & 15;
    if (i >= g_nf3) return;
    int n = g_list3[i];
    int beg = n * ELLW;
    int end = beg + min(g_cursor[n], ELLW);
    for (int e = beg + lane; e < end; e += 16) {
        int c = g_cedge[e].x;
        if (atomicExch(&g_flag2[c], 1) == 0) {
            int p = atomicAdd(&g_nf2, 1);
            g_list2[p] = c;
        }
    }
}

// ---------------- tiled transform (conflict-free), list modes ----------------
__global__ void __launch_bounds__(TTHREADS)
transform_kernel(const float* __restrict__ Wgc,
                 const float* __restrict__ bgc,
                 const float* __restrict__ Wbi,
                 const float* __restrict__ bbi,
                 int layer, int mode) {
    extern __shared__ char dsm[];
    unsigned long long* sPx = reinterpret_cast<unsigned long long*>(dsm);
    unsigned long long* sWc = sPx + TN * SPX_STRIDE;
    float* sb = reinterpret_cast<float*>(sWc + 8 * WCH_STRIDE);
    __shared__ int sNode[TN];

    const int tid = threadIdx.x;
    const int base = blockIdx.x * TN;

    if (tid < TN) {
        int idx = base + tid;
        int node = -1;
        if (mode == 0) {
            if (idx < N_NODESC) node = idx;
        } else if (mode == 2) {
            if (idx < g_nf2) node = g_list2[idx];
        } else {
            if (idx < g_nf3) node = g_list3[idx];
        }
        sNode[tid] = node;
    }

    {
        const float* w1g = Wgc + layer * EMB * EMB;
        const float* w2g = Wbi + layer * EMB * EMB;
        for (int i = tid; i < EMB * EMB; i += TTHREADS) {
            int k = i >> 6, j = i & 63;
            int c = j >> 3, ii = j & 7;
            sWc[c * WCH_STRIDE + k * 8 + ii] = pk2(w1g[i], w2g[i]);
        }
        if (tid < EMB)
            sb[tid] = bgc[layer * EMB + tid] + bbi[layer * EMB + tid];
    }
    __syncthreads();

    {
        const float4* ego4 = reinterpret_cast<const float4*>(g_ego);
        const float4* neigh4 = reinterpret_cast<const float4*>(g_neigh);
        float4* sPxF4 = reinterpret_cast<float4*>(sPx);
        for (int i = tid; i < TN * 16; i += TTHREADS) {
            int local = i >> 4;
            int kq = i & 15;
            int gn = sNode[local];
            float4 a, b;
            if (gn >= 0) {
                float4 n = neigh4[gn * 16 + kq];
                float4 e = ego4[gn * 16 + kq];
                a = make_float4(n.x, e.x * n.x, n.y, e.y * n.y);
                b = make_float4(n.z, e.z * n.z, n.w, e.w * n.w);
            } else {
                a = make_float4(0.f, 0.f, 0.f, 0.f);
                b = a;
            }
            sPxF4[local * (SPX_STRIDE / 2) + kq * 2]     = a;
            sPxF4[local * (SPX_STRIDE / 2) + kq * 2 + 1] = b;
        }
    }
    __syncthreads();

    const int g_n = tid >> 3;
    const int g_c = tid & 7;
    const int n0 = g_n * 2;
    const int c0 = g_c * 8;

    const unsigned long long* xA = sPx + (n0 + 0) * SPX_STRIDE;
    const unsigned long long* xB = sPx + (n0 + 1) * SPX_STRIDE;
    const unsigned long long* wch = sWc + g_c * WCH_STRIDE;

    unsigned long long acc0[8], acc1[8];
#pragma unroll
    for (int c = 0; c < 8; c++) {
        unsigned long long b = pk2(sb[c0 + c], 0.f);
        acc0[c] = b;
        acc1[c] = b;
    }

#pragma unroll 4
    for (int k = 0; k < EMB; k++) {
        unsigned long long a0 = xA[k];
        unsigned long long a1 = xB[k];
        const unsigned long long* wr = wch + k * 8;
#pragma unroll
        for (int c = 0; c < 8; c++) {
            unsigned long long w = wr[c];
            fma2(acc0[c], a0, w);
            fma2(acc1[c], a1, w);
        }
    }

    const unsigned mask = 0xffffffffu;
#pragma unroll
    for (int j = 0; j < 2; j++) {
        int gn = sNode[n0 + j];
        unsigned long long* accj = (j == 0) ? acc0 : acc1;
        float o[8];
        float s = 0.f;
#pragma unroll
        for (int c = 0; c < 8; c++) {
            float2 t = upk2(accj[c]);
            float v = t.x + t.y;
            v = (v >= 0.f) ? v : NEG_SLOPE * v;
            o[c] = v;
            s += v * v;
        }
        s += __shfl_xor_sync(mask, s, 1, 8);
        s += __shfl_xor_sync(mask, s, 2, 8);
        s += __shfl_xor_sync(mask, s, 4, 8);
        float sc = 1.0f / fmaxf(sqrtf(s), 1e-12f);

        if (gn >= 0) {
            float4 v0 = make_float4(o[0] * sc, o[1] * sc, o[2] * sc, o[3] * sc);
            float4 v1 = make_float4(o[4] * sc, o[5] * sc, o[6] * sc, o[7] * sc);
            float4* outr = reinterpret_cast<float4*>(g_ego + gn * EMB + c0);
            outr[0] = v0;
            outr[1] = v1;
            __half2 h0 = __float22half2_rn(make_float2(v0.x, v0.y));
            __half2 h1 = __float22half2_rn(make_float2(v0.z, v0.w));
            __half2 h2 = __float22half2_rn(make_float2(v1.x, v1.y));
            __half2 h3 = __float22half2_rn(make_float2(v1.z, v1.w));
            uint4 hp;
            hp.x = *reinterpret_cast<unsigned*>(&h0);
            hp.y = *reinterpret_cast<unsigned*>(&h1);
            hp.z = *reinterpret_cast<unsigned*>(&h2);
            hp.w = *reinterpret_cast<unsigned*>(&h3);
            *reinterpret_cast<uint4*>(reinterpret_cast<char*>(g_egoH) + gn * 128 + g_c * 16) = hp;
        }
    }
}

// ---------------- output gather ----------------
__global__ void gather_out_kernel(const int* __restrict__ users,
                                  const int* __restrict__ pos,
                                  const int* __restrict__ neg,
                                  float* __restrict__ out,
                                  int stage) {
    int gid = blockIdx.x * blockDim.x + threadIdx.x;
    int r = gid >> 4;
    if (r >= 3 * BATCHC) return;
    int g = gid & 15;
    int node;
    if (r < BATCHC) node = users[r];
    else if (r < 2 * BATCHC) node = N_USERS + pos[r - BATCHC];
    else node = N_USERS + neg[r - 2 * BATCHC];

    const float4* ego4 = reinterpret_cast<const float4*>(g_ego);
    float4 v = ego4[node * 16 + g];
    *reinterpret_cast<float4*>(&out[(size_t)r * (4 * EMB) + stage * EMB + g * 4]) = v;
}

// ---------------- launch ----------------
extern "C" void kernel_launch(void* const* d_in, const int* in_sizes, int n_in,
                              void* d_out, int out_size) {
    const int*   edge_row = (const int*)d_in[0];
    const int*   edge_col = (const int*)d_in[1];
    const float* edge_val = (const float*)d_in[2];
    const float* user_emb = (const float*)d_in[3];
    const float* item_emb = (const float*)d_in[4];
    const float* W_gc     = (const float*)d_in[5];
    const float* b_gc     = (const float*)d_in[6];
    const float* W_bi     = (const float*)d_in[7];
    const float* b_bi     = (const float*)d_in[8];
    const int*   users    = (const int*)d_in[9];
    const int*   pos      = (const int*)d_in[10];
    const int*   neg      = (const int*)d_in[11];
    float* out = (float*)d_out;

    const int T = 256;
    const int nbEdges = (N_EDGESC + T - 1) / T;        // 37500
    const int nbPrep = (N_NODESC * 16) / T;            // 18750
    const int nbNode8 = (N_NODESC * 8) / T;            // 9375
    const int nbGather = (3 * BATCHC * 16 + T - 1) / T;
    const int nbTrans = (N_NODESC + TN - 1) / TN;      // 4688
    const int nbProp = (3 * BATCHC * 16 + T - 1) / T;  // 768
    const int nbAgg3 = (3 * BATCHC * 8 + T - 1) / T;   // 384
    const int nbTrans3 = (3 * BATCHC + TN - 1) / TN;   // 192

    const int smemBytes = TN * SPX_STRIDE * 8 + 8 * WCH_STRIDE * 8 + EMB * 4 + TN * 4;
    cudaFuncSetAttribute(transform_kernel, cudaFuncAttributeMaxDynamicSharedMemorySize,
                         smemBytes);

    // 1: prep = zero + copy ego + stage-0 output
    prep_kernel<<<nbPrep, T>>>((const float4*)user_emb, (const float4*)item_emb,
                               users, pos, neg, out);
    // 2: ELL scatter + mark3
    scatter_kernel<<<nbEdges, T>>>(edge_row, edge_col, edge_val, users, pos, neg);
    // 3: layer-1 aggregate (8 lanes/node)
    aggregate_kernel<<<nbNode8, T>>>(0);
    // 4: layer-1 transform  <-- ncu profiled slot
    transform_kernel<<<nbTrans, TTHREADS, smemBytes>>>(W_gc, b_gc, W_bi, b_bi, 0, 0);

    // frontier-2 build (needs scatter + mark3)
    propagate_kernel<<<nbProp, T>>>();
    gather_out_kernel<<<nbGather, T>>>(users, pos, neg, out, 1);

    // layer 2: frontier F2
    aggregate_kernel<<<nbNode8, T>>>(2);
    transform_kernel<<<nbTrans, TTHREADS, smemBytes>>>(W_gc, b_gc, W_bi, b_bi, 1, 2);
    gather_out_kernel<<<nbGather, T>>>(users, pos, neg, out, 2);

    // layer 3: frontier F3
    aggregate_kernel<<<nbAgg3, T>>>(3);
    transform_kernel<<<nbTrans3, TTHREADS, smemBytes>>>(W_gc, b_gc, W_bi, b_bi, 2, 3);
    gather_out_kernel<<<nbGather, T>>>(users, pos, neg, out, 3);
}

// round 14
// speedup vs baseline: 1.1101x; 1.1101x over previous
#include <cuda_runtime.h>
#include <cuda_fp16.h>

#define N_USERS 100000
#define N_ITEMS 200000
#define N_NODESC 300000
#define EMB 64
#define NLAYERS 3
#define N_EDGESC 9600000
#define BATCHC 4096
#define NEG_SLOPE 0.2f

#define TN 64
#define TTHREADS 256
#define SPX_STRIDE 66   // ull per node row (64 + 2 pad); even -> 16B-aligned rows
#define WCH_STRIDE 514  // ull per weight chunk (512 + 2 pad); even -> 16B-aligned
#define ELLW 128        // ELL slots per node

typedef unsigned long long ull;

// ---------------- device scratch (no mallocs allowed) ----------------
__device__ float g_ego[N_NODESC * EMB];
__device__ uint2 g_egoH[N_NODESC * 16];
__device__ float g_neigh[N_NODESC * EMB];
__device__ int   g_cursor[N_NODESC];
__device__ int2  g_cedge[N_NODESC * ELLW];
// frontier machinery
__device__ int   g_flag2[N_NODESC];
__device__ int   g_flag3[N_NODESC];
__device__ int   g_list2[N_NODESC];
__device__ int   g_list3[3 * BATCHC];
__device__ int   g_nf2;
__device__ int   g_nf3;

// ---------------- f32x2 helpers ----------------
__device__ __forceinline__ void fma2(ull& d, ull a, ull b) {
    asm("fma.rn.f32x2 %0, %1, %2, %0;" : "+l"(d) : "l"(a), "l"(b));
}
__device__ __forceinline__ ull pk2(float lo, float hi) {
    ull r;
    asm("mov.b64 %0, {%1, %2};" : "=l"(r) : "f"(lo), "f"(hi));
    return r;
}
__device__ __forceinline__ float2 upk2(ull v) {
    float lo, hi;
    asm("mov.b64 {%0, %1}, %2;" : "=f"(lo), "=f"(hi) : "l"(v));
    return make_float2(lo, hi);
}

// ---------------- kernel 1: prep = zero + copy_ego + stage-0 output ----------------
__global__ void prep_kernel(const float4* __restrict__ ue,
                            const float4* __restrict__ ie,
                            const int* __restrict__ users,
                            const int* __restrict__ pos,
                            const int* __restrict__ neg,
                            float* __restrict__ out) {
    int gid = blockIdx.x * blockDim.x + threadIdx.x;

    if (gid < N_NODESC) {
        g_cursor[gid] = 0;
        g_flag2[gid] = 0;
        g_flag3[gid] = 0;
    }
    if (gid == 0) { g_nf2 = 0; g_nf3 = 0; }

    {
        float4* ego4 = reinterpret_cast<float4*>(g_ego);
        const int ucount = N_USERS * (EMB / 4);
        float4 v = (gid < ucount) ? ue[gid] : ie[gid - ucount];
        ego4[gid] = v;
        __half2 h0 = __float22half2_rn(make_float2(v.x, v.y));
        __half2 h1 = __float22half2_rn(make_float2(v.z, v.w));
        uint2 p;
        p.x = *reinterpret_cast<unsigned*>(&h0);
        p.y = *reinterpret_cast<unsigned*>(&h1);
        g_egoH[gid] = p;
    }

    if (gid < 3 * BATCHC * 16) {
        int r = gid >> 4;
        int g = gid & 15;
        float4 v;
        if (r < BATCHC) {
            v = ue[users[r] * 16 + g];
        } else if (r < 2 * BATCHC) {
            v = ie[pos[r - BATCHC] * 16 + g];
        } else {
            v = ie[neg[r - 2 * BATCHC] * 16 + g];
        }
        *reinterpret_cast<float4*>(&out[(size_t)r * (4 * EMB) + g * 4]) = v;
    }
}

// ---------------- kernel 2: ELL scatter + mark3 ----------------
__global__ void scatter_kernel(const int* __restrict__ row,
                               const int* __restrict__ col,
                               const float* __restrict__ val,
                               const int* __restrict__ users,
                               const int* __restrict__ pos,
                               const int* __restrict__ neg) {
    int e = blockIdx.x * blockDim.x + threadIdx.x;
    if (e >= N_EDGESC) return;
    int r = row[e];
    int p = atomicAdd(&g_cursor[r], 1);
    if (p < ELLW)
        g_cedge[r * ELLW + p] = make_int2(col[e], __float_as_int(val[e]));

    if (e < 3 * BATCHC) {
        int n;
        if (e < BATCHC) n = users[e];
        else if (e < 2 * BATCHC) n = N_USERS + pos[e - BATCHC];
        else n = N_USERS + neg[e - 2 * BATCHC];
        if (atomicExch(&g_flag3[n], 1) == 0) {
            int q = atomicAdd(&g_nf3, 1);
            g_list3[q] = n;
        }
        if (atomicExch(&g_flag2[n], 1) == 0) {
            int q = atomicAdd(&g_nf2, 1);
            g_list2[q] = n;
        }
    }
}

// ---------------- kernel 3: aggregation, 8 lanes/node ----------------
__global__ void aggregate_kernel(int mode) {
    int gid = blockIdx.x * blockDim.x + threadIdx.x;
    int i = gid >> 3;
    int g = gid & 7;
    int node;
    if (mode == 0) {
        node = i;
        if (node >= N_NODESC) return;
    } else if (mode == 2) {
        if (i >= g_nf2) return;
        node = g_list2[i];
    } else {
        if (i >= g_nf3) return;
        node = g_list3[i];
    }
    const uint4* egoH4 = reinterpret_cast<const uint4*>(g_egoH);

    int cnt = min(g_cursor[node], ELLW);
    int beg = node * ELLW;
    int end = beg + cnt;
    float a0 = 0.f, a1 = 0.f, a2 = 0.f, a3 = 0.f;
    float a4 = 0.f, a5 = 0.f, a6 = 0.f, a7 = 0.f;
#pragma unroll 4
    for (int e = beg; e < end; e++) {
        int2 ev = g_cedge[e];
        float v = __int_as_float(ev.y);
        uint4 p = egoH4[ev.x * 8 + g];
        float2 f0 = __half22float2(*reinterpret_cast<__half2*>(&p.x));
        float2 f1 = __half22float2(*reinterpret_cast<__half2*>(&p.y));
        float2 f2 = __half22float2(*reinterpret_cast<__half2*>(&p.z));
        float2 f3 = __half22float2(*reinterpret_cast<__half2*>(&p.w));
        a0 += v * f0.x; a1 += v * f0.y;
        a2 += v * f1.x; a3 += v * f1.y;
        a4 += v * f2.x; a5 += v * f2.y;
        a6 += v * f3.x; a7 += v * f3.y;
    }
    float* nr = g_neigh + node * EMB + g * 8;
    *reinterpret_cast<float4*>(nr)     = make_float4(a0, a1, a2, a3);
    *reinterpret_cast<float4*>(nr + 4) = make_float4(a4, a5, a6, a7);
}

// ---------------- frontier propagate ----------------
__global__ void propagate_kernel() {
    int gid = blockIdx.x * blockDim.x + threadIdx.x;
    int i = gid >> 4;
    int lane = gid & 15;
    if (i >= g_nf3) return;
    int n = g_list3[i];
    int beg = n * ELLW;
    int end = beg + min(g_cursor[n], ELLW);
    for (int e = beg + lane; e < end; e += 16) {
        int c = g_cedge[e].x;
        if (atomicExch(&g_flag2[c], 1) == 0) {
            int p = atomicAdd(&g_nf2, 1);
            g_list2[p] = c;
        }
    }
}

// ---------------- tiled transform: 128-bit smem loads in the mainloop ----------------
__global__ void __launch_bounds__(TTHREADS)
transform_kernel(const float* __restrict__ Wgc,
                 const float* __restrict__ bgc,
                 const float* __restrict__ Wbi,
                 const float* __restrict__ bbi,
                 int layer, int mode) {
    extern __shared__ char dsm[];
    ull* sPx = reinterpret_cast<ull*>(dsm);
    ull* sWc = sPx + TN * SPX_STRIDE;
    float* sb = reinterpret_cast<float*>(sWc + 8 * WCH_STRIDE);
    __shared__ int sNode[TN];

    const int tid = threadIdx.x;
    const int base = blockIdx.x * TN;

    if (tid < TN) {
        int idx = base + tid;
        int node = -1;
        if (mode == 0) {
            if (idx < N_NODESC) node = idx;
        } else if (mode == 2) {
            if (idx < g_nf2) node = g_list2[idx];
        } else {
            if (idx < g_nf3) node = g_list3[idx];
        }
        sNode[tid] = node;
    }

    {
        const float* w1g = Wgc + layer * EMB * EMB;
        const float* w2g = Wbi + layer * EMB * EMB;
        for (int i = tid; i < EMB * EMB; i += TTHREADS) {
            int k = i >> 6, j = i & 63;
            int c = j >> 3, ii = j & 7;
            sWc[c * WCH_STRIDE + k * 8 + ii] = pk2(w1g[i], w2g[i]);
        }
        if (tid < EMB)
            sb[tid] = bgc[layer * EMB + tid] + bbi[layer * EMB + tid];
    }
    __syncthreads();

    {
        const float4* ego4 = reinterpret_cast<const float4*>(g_ego);
        const float4* neigh4 = reinterpret_cast<const float4*>(g_neigh);
        float4* sPxF4 = reinterpret_cast<float4*>(sPx);
        for (int i = tid; i < TN * 16; i += TTHREADS) {
            int local = i >> 4;
            int kq = i & 15;
            int gn = sNode[local];
            float4 a, b;
            if (gn >= 0) {
                float4 n = neigh4[gn * 16 + kq];
                float4 e = ego4[gn * 16 + kq];
                a = make_float4(n.x, e.x * n.x, n.y, e.y * n.y);
                b = make_float4(n.z, e.z * n.z, n.w, e.w * n.w);
            } else {
                a = make_float4(0.f, 0.f, 0.f, 0.f);
                b = a;
            }
            sPxF4[local * (SPX_STRIDE / 2) + kq * 2]     = a;
            sPxF4[local * (SPX_STRIDE / 2) + kq * 2 + 1] = b;
        }
    }
    __syncthreads();

    const int g_n = tid >> 3;
    const int g_c = tid & 7;
    const int n0 = g_n * 2;
    const int c0 = g_c * 8;

    const ulonglong2* xA2 = reinterpret_cast<const ulonglong2*>(sPx + (n0 + 0) * SPX_STRIDE);
    const ulonglong2* xB2 = reinterpret_cast<const ulonglong2*>(sPx + (n0 + 1) * SPX_STRIDE);
    const ull* wch = sWc + g_c * WCH_STRIDE;

    ull acc0[8], acc1[8];
#pragma unroll
    for (int c = 0; c < 8; c++) {
        ull b = pk2(sb[c0 + c], 0.f);
        acc0[c] = b;
        acc1[c] = b;
    }

    // mainloop: 2 k-steps per iter, all smem traffic via LDS.128
#pragma unroll 8
    for (int k2 = 0; k2 < EMB / 2; k2++) {
        ulonglong2 a0 = xA2[k2];   // (px[2k2], px[2k2+1]) node A
        ulonglong2 a1 = xB2[k2];   // node B
        const ulonglong2* wr0 = reinterpret_cast<const ulonglong2*>(wch + (2 * k2) * 8);
        const ulonglong2* wr1 = reinterpret_cast<const ulonglong2*>(wch + (2 * k2 + 1) * 8);
#pragma unroll
        for (int c2 = 0; c2 < 4; c2++) {
            ulonglong2 w0 = wr0[c2];
            ulonglong2 w1 = wr1[c2];
            fma2(acc0[2 * c2],     a0.x, w0.x);
            fma2(acc0[2 * c2 + 1], a0.x, w0.y);
            fma2(acc1[2 * c2],     a1.x, w0.x);
            fma2(acc1[2 * c2 + 1], a1.x, w0.y);
            fma2(acc0[2 * c2],     a0.y, w1.x);
            fma2(acc0[2 * c2 + 1], a0.y, w1.y);
            fma2(acc1[2 * c2],     a1.y, w1.x);
            fma2(acc1[2 * c2 + 1], a1.y, w1.y);
        }
    }

    const unsigned mask = 0xffffffffu;
#pragma unroll
    for (int j = 0; j < 2; j++) {
        int gn = sNode[n0 + j];
        ull* accj = (j == 0) ? acc0 : acc1;
        float o[8];
        float s = 0.f;
#pragma unroll
        for (int c = 0; c < 8; c++) {
            float2 t = upk2(accj[c]);
            float v = t.x + t.y;
            v = (v >= 0.f) ? v : NEG_SLOPE * v;
            o[c] = v;
            s += v * v;
        }
        s += __shfl_xor_sync(mask, s, 1, 8);
        s += __shfl_xor_sync(mask, s, 2, 8);
        s += __shfl_xor_sync(mask, s, 4, 8);
        float sc = 1.0f / fmaxf(sqrtf(s), 1e-12f);

        if (gn >= 0) {
            float4 v0 = make_float4(o[0] * sc, o[1] * sc, o[2] * sc, o[3] * sc);
            float4 v1 = make_float4(o[4] * sc, o[5] * sc, o[6] * sc, o[7] * sc);
            float4* outr = reinterpret_cast<float4*>(g_ego + gn * EMB + c0);
            outr[0] = v0;
            outr[1] = v1;
            __half2 h0 = __float22half2_rn(make_float2(v0.x, v0.y));
            __half2 h1 = __float22half2_rn(make_float2(v0.z, v0.w));
            __half2 h2 = __float22half2_rn(make_float2(v1.x, v1.y));
            __half2 h3 = __float22half2_rn(make_float2(v1.z, v1.w));
            uint4 hp;
            hp.x = *reinterpret_cast<unsigned*>(&h0);
            hp.y = *reinterpret_cast<unsigned*>(&h1);
            hp.z = *reinterpret_cast<unsigned*>(&h2);
            hp.w = *reinterpret_cast<unsigned*>(&h3);
            *reinterpret_cast<uint4*>(reinterpret_cast<char*>(g_egoH) + gn * 128 + g_c * 16) = hp;
        }
    }
}

// ---------------- output gather ----------------
__global__ void gather_out_kernel(const int* __restrict__ users,
                                  const int* __restrict__ pos,
                                  const int* __restrict__ neg,
                                  float* __restrict__ out,
                                  int stage) {
    int gid = blockIdx.x * blockDim.x + threadIdx.x;
    int r = gid >> 4;
    if (r >= 3 * BATCHC) return;
    int g = gid & 15;
    int node;
    if (r < BATCHC) node = users[r];
    else if (r < 2 * BATCHC) node = N_USERS + pos[r - BATCHC];
    else node = N_USERS + neg[r - 2 * BATCHC];

    const float4* ego4 = reinterpret_cast<const float4*>(g_ego);
    float4 v = ego4[node * 16 + g];
    *reinterpret_cast<float4*>(&out[(size_t)r * (4 * EMB) + stage * EMB + g * 4]) = v;
}

// ---------------- launch ----------------
extern "C" void kernel_launch(void* const* d_in, const int* in_sizes, int n_in,
                              void* d_out, int out_size) {
    const int*   edge_row = (const int*)d_in[0];
    const int*   edge_col = (const int*)d_in[1];
    const float* edge_val = (const float*)d_in[2];
    const float* user_emb = (const float*)d_in[3];
    const float* item_emb = (const float*)d_in[4];
    const float* W_gc     = (const float*)d_in[5];
    const float* b_gc     = (const float*)d_in[6];
    const float* W_bi     = (const float*)d_in[7];
    const float* b_bi     = (const float*)d_in[8];
    const int*   users    = (const int*)d_in[9];
    const int*   pos      = (const int*)d_in[10];
    const int*   neg      = (const int*)d_in[11];
    float* out = (float*)d_out;

    const int T = 256;
    const int nbEdges = (N_EDGESC + T - 1) / T;        // 37500
    const int nbPrep = (N_NODESC * 16) / T;            // 18750
    const int nbNode8 = (N_NODESC * 8) / T;            // 9375
    const int nbGather = (3 * BATCHC * 16 + T - 1) / T;
    const int nbTrans = (N_NODESC + TN - 1) / TN;      // 4688
    const int nbProp = (3 * BATCHC * 16 + T - 1) / T;  // 768
    const int nbAgg3 = (3 * BATCHC * 8 + T - 1) / T;   // 384
    const int nbTrans3 = (3 * BATCHC + TN - 1) / TN;   // 192

    const int smemBytes = TN * SPX_STRIDE * 8 + 8 * WCH_STRIDE * 8 + EMB * 4 + TN * 4;
    cudaFuncSetAttribute(transform_kernel, cudaFuncAttributeMaxDynamicSharedMemorySize,
                         smemBytes);

    // 1: prep = zero + copy ego + stage-0 output
    prep_kernel<<<nbPrep, T>>>((const float4*)user_emb, (const float4*)item_emb,
                               users, pos, neg, out);
    // 2: ELL scatter + mark3
    scatter_kernel<<<nbEdges, T>>>(edge_row, edge_col, edge_val, users, pos, neg);
    // 3: layer-1 aggregate
    aggregate_kernel<<<nbNode8, T>>>(0);
    // 4: layer-1 transform  <-- ncu profiled slot (A/B vs round 12)
    transform_kernel<<<nbTrans, TTHREADS, smemBytes>>>(W_gc, b_gc, W_bi, b_bi, 0, 0);

    propagate_kernel<<<nbProp, T>>>();
    gather_out_kernel<<<nbGather, T>>>(users, pos, neg, out, 1);

    // layer 2: frontier F2
    aggregate_kernel<<<nbNode8, T>>>(2);
    transform_kernel<<<nbTrans, TTHREADS, smemBytes>>>(W_gc, b_gc, W_bi, b_bi, 1, 2);
    gather_out_kernel<<<nbGather, T>>>(users, pos, neg, out, 2);

    // layer 3: frontier F3
    aggregate_kernel<<<nbAgg3, T>>>(3);
    transform_kernel<<<nbTrans3, TTHREADS, smemBytes>>>(W_gc, b_gc, W_bi, b_bi, 2, 3);
    gather_out_kernel<<<nbGather, T>>>(users, pos, neg, out, 3);
}

// round 15
// speedup vs baseline: 1.2400x; 1.1170x over previous
#include <cuda_runtime.h>
#include <cuda_fp16.h>

#define N_USERS 100000
#define N_ITEMS 200000
#define N_NODESC 300000
#define EMB 64
#define NLAYERS 3
#define N_EDGESC 9600000
#define BATCHC 4096
#define NEG_SLOPE 0.2f

#define TN 128          // nodes per transform block (4 per thread)
#define TTHREADS 256
#define SPX_STRIDE 66   // ull per node row (64 + 2 pad); even -> 16B-aligned rows
#define WCH_STRIDE 514  // ull per weight chunk (512 + 2 pad); even -> 16B-aligned
#define ELLW 128        // ELL slots per node

typedef unsigned long long ull;

// ---------------- device scratch (no mallocs allowed) ----------------
__device__ float g_ego[N_NODESC * EMB];
__device__ uint2 g_egoH[N_NODESC * 16];
__device__ float g_neigh[N_NODESC * EMB];
__device__ int   g_cursor[N_NODESC];
__device__ int2  g_cedge[N_NODESC * ELLW];
// frontier machinery
__device__ int   g_flag2[N_NODESC];
__device__ int   g_flag3[N_NODESC];
__device__ int   g_list2[N_NODESC];
__device__ int   g_list3[3 * BATCHC];
__device__ int   g_nf2;
__device__ int   g_nf3;

// ---------------- f32x2 helpers ----------------
__device__ __forceinline__ void fma2(ull& d, ull a, ull b) {
    asm("fma.rn.f32x2 %0, %1, %2, %0;" : "+l"(d) : "l"(a), "l"(b));
}
__device__ __forceinline__ ull pk2(float lo, float hi) {
    ull r;
    asm("mov.b64 %0, {%1, %2};" : "=l"(r) : "f"(lo), "f"(hi));
    return r;
}
__device__ __forceinline__ float2 upk2(ull v) {
    float lo, hi;
    asm("mov.b64 {%0, %1}, %2;" : "=f"(lo), "=f"(hi) : "l"(v));
    return make_float2(lo, hi);
}

// ---------------- kernel 1: prep = zero + copy_ego + stage-0 output ----------------
__global__ void prep_kernel(const float4* __restrict__ ue,
                            const float4* __restrict__ ie,
                            const int* __restrict__ users,
                            const int* __restrict__ pos,
                            const int* __restrict__ neg,
                            float* __restrict__ out) {
    int gid = blockIdx.x * blockDim.x + threadIdx.x;

    if (gid < N_NODESC) {
        g_cursor[gid] = 0;
        g_flag2[gid] = 0;
        g_flag3[gid] = 0;
    }
    if (gid == 0) { g_nf2 = 0; g_nf3 = 0; }

    {
        float4* ego4 = reinterpret_cast<float4*>(g_ego);
        const int ucount = N_USERS * (EMB / 4);
        float4 v = (gid < ucount) ? ue[gid] : ie[gid - ucount];
        ego4[gid] = v;
        __half2 h0 = __float22half2_rn(make_float2(v.x, v.y));
        __half2 h1 = __float22half2_rn(make_float2(v.z, v.w));
        uint2 p;
        p.x = *reinterpret_cast<unsigned*>(&h0);
        p.y = *reinterpret_cast<unsigned*>(&h1);
        g_egoH[gid] = p;
    }

    if (gid < 3 * BATCHC * 16) {
        int r = gid >> 4;
        int g = gid & 15;
        float4 v;
        if (r < BATCHC) {
            v = ue[users[r] * 16 + g];
        } else if (r < 2 * BATCHC) {
            v = ie[pos[r - BATCHC] * 16 + g];
        } else {
            v = ie[neg[r - 2 * BATCHC] * 16 + g];
        }
        *reinterpret_cast<float4*>(&out[(size_t)r * (4 * EMB) + g * 4]) = v;
    }
}

// ---------------- kernel 2: ELL scatter + mark3 ----------------
__global__ void scatter_kernel(const int* __restrict__ row,
                               const int* __restrict__ col,
                               const float* __restrict__ val,
                               const int* __restrict__ users,
                               const int* __restrict__ pos,
                               const int* __restrict__ neg) {
    int e = blockIdx.x * blockDim.x + threadIdx.x;
    if (e >= N_EDGESC) return;
    int r = row[e];
    int p = atomicAdd(&g_cursor[r], 1);
    if (p < ELLW)
        g_cedge[r * ELLW + p] = make_int2(col[e], __float_as_int(val[e]));

    if (e < 3 * BATCHC) {
        int n;
        if (e < BATCHC) n = users[e];
        else if (e < 2 * BATCHC) n = N_USERS + pos[e - BATCHC];
        else n = N_USERS + neg[e - 2 * BATCHC];
        if (atomicExch(&g_flag3[n], 1) == 0) {
            int q = atomicAdd(&g_nf3, 1);
            g_list3[q] = n;
        }
        if (atomicExch(&g_flag2[n], 1) == 0) {
            int q = atomicAdd(&g_nf2, 1);
            g_list2[q] = n;
        }
    }
}

// ---------------- kernel 3: aggregation, 8 lanes/node ----------------
__global__ void aggregate_kernel(int mode) {
    int gid = blockIdx.x * blockDim.x + threadIdx.x;
    int i = gid >> 3;
    int g = gid & 7;
    int node;
    if (mode == 0) {
        node = i;
        if (node >= N_NODESC) return;
    } else if (mode == 2) {
        if (i >= g_nf2) return;
        node = g_list2[i];
    } else {
        if (i >= g_nf3) return;
        node = g_list3[i];
    }
    const uint4* egoH4 = reinterpret_cast<const uint4*>(g_egoH);

    int cnt = min(g_cursor[node], ELLW);
    int beg = node * ELLW;
    int end = beg + cnt;
    float a0 = 0.f, a1 = 0.f, a2 = 0.f, a3 = 0.f;
    float a4 = 0.f, a5 = 0.f, a6 = 0.f, a7 = 0.f;
#pragma unroll 4
    for (int e = beg; e < end; e++) {
        int2 ev = g_cedge[e];
        float v = __int_as_float(ev.y);
        uint4 p = egoH4[ev.x * 8 + g];
        float2 f0 = __half22float2(*reinterpret_cast<__half2*>(&p.x));
        float2 f1 = __half22float2(*reinterpret_cast<__half2*>(&p.y));
        float2 f2 = __half22float2(*reinterpret_cast<__half2*>(&p.z));
        float2 f3 = __half22float2(*reinterpret_cast<__half2*>(&p.w));
        a0 += v * f0.x; a1 += v * f0.y;
        a2 += v * f1.x; a3 += v * f1.y;
        a4 += v * f2.x; a5 += v * f2.y;
        a6 += v * f3.x; a7 += v * f3.y;
    }
    float* nr = g_neigh + node * EMB + g * 8;
    *reinterpret_cast<float4*>(nr)     = make_float4(a0, a1, a2, a3);
    *reinterpret_cast<float4*>(nr + 4) = make_float4(a4, a5, a6, a7);
}

// ---------------- frontier propagate ----------------
__global__ void propagate_kernel() {
    int gid = blockIdx.x * blockDim.x + threadIdx.x;
    int i = gid >> 4;
    int lane = gid & 15;
    if (i >= g_nf3) return;
    int n = g_list3[i];
    int beg = n * ELLW;
    int end = beg + min(g_cursor[n], ELLW);
    for (int e = beg + lane; e < end; e += 16) {
        int c = g_cedge[e].x;
        if (atomicExch(&g_flag2[c], 1) == 0) {
            int p = atomicAdd(&g_nf2, 1);
            g_list2[p] = c;
        }
    }
}

// ---------------- tiled transform v3: 4 nodes x 8 cols per thread ----------------
__global__ void __launch_bounds__(TTHREADS, 2)
transform_kernel(const float* __restrict__ Wgc,
                 const float* __restrict__ bgc,
                 const float* __restrict__ Wbi,
                 const float* __restrict__ bbi,
                 int layer, int mode) {
    extern __shared__ char dsm[];
    ull* sPx = reinterpret_cast<ull*>(dsm);                 // TN * 66 ull
    ull* sWc = sPx + TN * SPX_STRIDE;                       // 8 * 514 ull
    float* sb = reinterpret_cast<float*>(sWc + 8 * WCH_STRIDE);
    int* sNode = reinterpret_cast<int*>(sb + EMB);

    const int tid = threadIdx.x;
    const int base = blockIdx.x * TN;

    if (tid < TN) {
        int idx = base + tid;
        int node = -1;
        if (mode == 0) {
            if (idx < N_NODESC) node = idx;
        } else if (mode == 2) {
            if (idx < g_nf2) node = g_list2[idx];
        } else {
            if (idx < g_nf3) node = g_list3[idx];
        }
        sNode[tid] = node;
    }

    {
        const float* w1g = Wgc + layer * EMB * EMB;
        const float* w2g = Wbi + layer * EMB * EMB;
        for (int i = tid; i < EMB * EMB; i += TTHREADS) {
            int k = i >> 6, j = i & 63;
            int c = j >> 3, ii = j & 7;
            sWc[c * WCH_STRIDE + k * 8 + ii] = pk2(w1g[i], w2g[i]);
        }
        if (tid < EMB)
            sb[tid] = bgc[layer * EMB + tid] + bbi[layer * EMB + tid];
    }
    __syncthreads();

    {
        const float4* ego4 = reinterpret_cast<const float4*>(g_ego);
        const float4* neigh4 = reinterpret_cast<const float4*>(g_neigh);
        float4* sPxF4 = reinterpret_cast<float4*>(sPx);
        for (int i = tid; i < TN * 16; i += TTHREADS) {
            int local = i >> 4;
            int kq = i & 15;
            int gn = sNode[local];
            float4 a, b;
            if (gn >= 0) {
                float4 n = neigh4[gn * 16 + kq];
                float4 e = ego4[gn * 16 + kq];
                a = make_float4(n.x, e.x * n.x, n.y, e.y * n.y);
                b = make_float4(n.z, e.z * n.z, n.w, e.w * n.w);
            } else {
                a = make_float4(0.f, 0.f, 0.f, 0.f);
                b = a;
            }
            sPxF4[local * (SPX_STRIDE / 2) + kq * 2]     = a;
            sPxF4[local * (SPX_STRIDE / 2) + kq * 2 + 1] = b;
        }
    }
    __syncthreads();

    const int g_n = tid >> 3;    // node group 0..31 (4 nodes each)
    const int g_c = tid & 7;     // col chunk 0..7
    const int n0 = g_n * 4;
    const int c0 = g_c * 8;

    const ulonglong2* x0 = reinterpret_cast<const ulonglong2*>(sPx + (n0 + 0) * SPX_STRIDE);
    const ulonglong2* x1 = reinterpret_cast<const ulonglong2*>(sPx + (n0 + 1) * SPX_STRIDE);
    const ulonglong2* x2 = reinterpret_cast<const ulonglong2*>(sPx + (n0 + 2) * SPX_STRIDE);
    const ulonglong2* x3 = reinterpret_cast<const ulonglong2*>(sPx + (n0 + 3) * SPX_STRIDE);
    const ull* wch = sWc + g_c * WCH_STRIDE;

    ull acc0[8], acc1[8], acc2[8], acc3[8];
#pragma unroll
    for (int c = 0; c < 8; c++) {
        ull b = pk2(sb[c0 + c], 0.f);
        acc0[c] = b; acc1[c] = b; acc2[c] = b; acc3[c] = b;
    }

    // mainloop: 2 k-steps per iter, 4 nodes, all smem via LDS.128
#pragma unroll 4
    for (int k2 = 0; k2 < EMB / 2; k2++) {
        ulonglong2 a0 = x0[k2];
        ulonglong2 a1 = x1[k2];
        ulonglong2 a2 = x2[k2];
        ulonglong2 a3 = x3[k2];
        const ulonglong2* wr0 = reinterpret_cast<const ulonglong2*>(wch + (2 * k2) * 8);
        const ulonglong2* wr1 = reinterpret_cast<const ulonglong2*>(wch + (2 * k2 + 1) * 8);
#pragma unroll
        for (int c2 = 0; c2 < 4; c2++) {
            ulonglong2 w0 = wr0[c2];
            ulonglong2 w1 = wr1[c2];
            fma2(acc0[2 * c2],     a0.x, w0.x);
            fma2(acc0[2 * c2 + 1], a0.x, w0.y);
            fma2(acc1[2 * c2],     a1.x, w0.x);
            fma2(acc1[2 * c2 + 1], a1.x, w0.y);
            fma2(acc2[2 * c2],     a2.x, w0.x);
            fma2(acc2[2 * c2 + 1], a2.x, w0.y);
            fma2(acc3[2 * c2],     a3.x, w0.x);
            fma2(acc3[2 * c2 + 1], a3.x, w0.y);
            fma2(acc0[2 * c2],     a0.y, w1.x);
            fma2(acc0[2 * c2 + 1], a0.y, w1.y);
            fma2(acc1[2 * c2],     a1.y, w1.x);
            fma2(acc1[2 * c2 + 1], a1.y, w1.y);
            fma2(acc2[2 * c2],     a2.y, w1.x);
            fma2(acc2[2 * c2 + 1], a2.y, w1.y);
            fma2(acc3[2 * c2],     a3.y, w1.x);
            fma2(acc3[2 * c2 + 1], a3.y, w1.y);
        }
    }

    const unsigned mask = 0xffffffffu;
#pragma unroll
    for (int j = 0; j < 4; j++) {
        int gn = sNode[n0 + j];
        ull* accj = (j == 0) ? acc0 : (j == 1) ? acc1 : (j == 2) ? acc2 : acc3;
        float o[8];
        float s = 0.f;
#pragma unroll
        for (int c = 0; c < 8; c++) {
            float2 t = upk2(accj[c]);
            float v = t.x + t.y;
            v = (v >= 0.f) ? v : NEG_SLOPE * v;
            o[c] = v;
            s += v * v;
        }
        s += __shfl_xor_sync(mask, s, 1, 8);
        s += __shfl_xor_sync(mask, s, 2, 8);
        s += __shfl_xor_sync(mask, s, 4, 8);
        float sc = 1.0f / fmaxf(sqrtf(s), 1e-12f);

        if (gn >= 0) {
            float4 v0 = make_float4(o[0] * sc, o[1] * sc, o[2] * sc, o[3] * sc);
            float4 v1 = make_float4(o[4] * sc, o[5] * sc, o[6] * sc, o[7] * sc);
            float4* outr = reinterpret_cast<float4*>(g_ego + gn * EMB + c0);
            outr[0] = v0;
            outr[1] = v1;
            __half2 h0 = __float22half2_rn(make_float2(v0.x, v0.y));
            __half2 h1 = __float22half2_rn(make_float2(v0.z, v0.w));
            __half2 h2 = __float22half2_rn(make_float2(v1.x, v1.y));
            __half2 h3 = __float22half2_rn(make_float2(v1.z, v1.w));
            uint4 hp;
            hp.x = *reinterpret_cast<unsigned*>(&h0);
            hp.y = *reinterpret_cast<unsigned*>(&h1);
            hp.z = *reinterpret_cast<unsigned*>(&h2);
            hp.w = *reinterpret_cast<unsigned*>(&h3);
            *reinterpret_cast<uint4*>(reinterpret_cast<char*>(g_egoH) + gn * 128 + g_c * 16) = hp;
        }
    }
}

// ---------------- output gather ----------------
__global__ void gather_out_kernel(const int* __restrict__ users,
                                  const int* __restrict__ pos,
                                  const int* __restrict__ neg,
                                  float* __restrict__ out,
                                  int stage) {
    int gid = blockIdx.x * blockDim.x + threadIdx.x;
    int r = gid >> 4;
    if (r >= 3 * BATCHC) return;
    int g = gid & 15;
    int node;
    if (r < BATCHC) node = users[r];
    else if (r < 2 * BATCHC) node = N_USERS + pos[r - BATCHC];
    else node = N_USERS + neg[r - 2 * BATCHC];

    const float4* ego4 = reinterpret_cast<const float4*>(g_ego);
    float4 v = ego4[node * 16 + g];
    *reinterpret_cast<float4*>(&out[(size_t)r * (4 * EMB) + stage * EMB + g * 4]) = v;
}

// ---------------- launch ----------------
extern "C" void kernel_launch(void* const* d_in, const int* in_sizes, int n_in,
                              void* d_out, int out_size) {
    const int*   edge_row = (const int*)d_in[0];
    const int*   edge_col = (const int*)d_in[1];
    const float* edge_val = (const float*)d_in[2];
    const float* user_emb = (const float*)d_in[3];
    const float* item_emb = (const float*)d_in[4];
    const float* W_gc     = (const float*)d_in[5];
    const float* b_gc     = (const float*)d_in[6];
    const float* W_bi     = (const float*)d_in[7];
    const float* b_bi     = (const float*)d_in[8];
    const int*   users    = (const int*)d_in[9];
    const int*   pos      = (const int*)d_in[10];
    const int*   neg      = (const int*)d_in[11];
    float* out = (float*)d_out;

    const int T = 256;
    const int nbEdges = (N_EDGESC + T - 1) / T;        // 37500
    const int nbPrep = (N_NODESC * 16) / T;            // 18750
    const int nbNode8 = (N_NODESC * 8) / T;            // 9375
    const int nbGather = (3 * BATCHC * 16 + T - 1) / T;
    const int nbTrans = (N_NODESC + TN - 1) / TN;      // 2344
    const int nbProp = (3 * BATCHC * 16 + T - 1) / T;  // 768
    const int nbAgg3 = (3 * BATCHC * 8 + T - 1) / T;   // 384
    const int nbTrans3 = (3 * BATCHC + TN - 1) / TN;   // 96

    const int smemBytes = TN * SPX_STRIDE * 8 + 8 * WCH_STRIDE * 8 + EMB * 4 + TN * 4;
    cudaFuncSetAttribute(transform_kernel, cudaFuncAttributeMaxDynamicSharedMemorySize,
                         smemBytes);

    // 1: prep = zero + copy ego + stage-0 output
    prep_kernel<<<nbPrep, T>>>((const float4*)user_emb, (const float4*)item_emb,
                               users, pos, neg, out);
    // 2: ELL scatter + mark3
    scatter_kernel<<<nbEdges, T>>>(edge_row, edge_col, edge_val, users, pos, neg);
    // 3: layer-1 aggregate
    aggregate_kernel<<<nbNode8, T>>>(0);
    // 4: layer-1 transform  <-- ncu profiled slot (A/B vs round 13)
    transform_kernel<<<nbTrans, TTHREADS, smemBytes>>>(W_gc, b_gc, W_bi, b_bi, 0, 0);

    propagate_kernel<<<nbProp, T>>>();
    gather_out_kernel<<<nbGather, T>>>(users, pos, neg, out, 1);

    // layer 2: frontier F2
    aggregate_kernel<<<nbNode8, T>>>(2);
    transform_kernel<<<nbTrans, TTHREADS, smemBytes>>>(W_gc, b_gc, W_bi, b_bi, 1, 2);
    gather_out_kernel<<<nbGather, T>>>(users, pos, neg, out, 2);

    // layer 3: frontier F3
    aggregate_kernel<<<nbAgg3, T>>>(3);
    transform_kernel<<<nbTrans3, TTHREADS, smemBytes>>>(W_gc, b_gc, W_bi, b_bi, 2, 3);
    gather_out_kernel<<<nbGather, T>>>(users, pos, neg, out, 3);
}

// round 16
// speedup vs baseline: 1.5658x; 1.2627x over previous
#include <cuda_runtime.h>
#include <cuda_fp16.h>

#define N_USERS 100000
#define N_ITEMS 200000
#define N_NODESC 300000
#define EMB 64
#define NLAYERS 3
#define N_EDGESC 9600000
#define BATCHC 4096
#define NEG_SLOPE 0.2f

#define TN 128          // nodes per transform block
#define TTHREADS 256    // 8 warps x 16 nodes
#define ELLW 128        // ELL slots per node

// transform smem layout (bytes)
#define SX_OFF 0            // X fp16: 128 rows x 256 B (swizzled chunks)
#define SW_OFF 32768        // W fp16: 128 rows x 128 B (swizzled chunks)
#define SB_OFF 49152        // bias fp32: 64 floats
#define SN_OFF 49408        // node ids: 128 ints
#define SMEM_TOTAL 49920

typedef unsigned long long ull;

// ---------------- device scratch (no mallocs allowed) ----------------
__device__ float g_ego[N_NODESC * EMB];
__device__ uint2 g_egoH[N_NODESC * 16];
__device__ float g_neigh[N_NODESC * EMB];
__device__ int   g_cursor[N_NODESC];
__device__ int2  g_cedge[N_NODESC * ELLW];
// frontier machinery
__device__ int   g_flag2[N_NODESC];
__device__ int   g_flag3[N_NODESC];
__device__ int   g_list2[N_NODESC];
__device__ int   g_list3[3 * BATCHC];
__device__ int   g_nf2;
__device__ int   g_nf3;

// ---------------- kernel 1: prep = zero + copy_ego + stage-0 output ----------------
__global__ void prep_kernel(const float4* __restrict__ ue,
                            const float4* __restrict__ ie,
                            const int* __restrict__ users,
                            const int* __restrict__ pos,
                            const int* __restrict__ neg,
                            float* __restrict__ out) {
    int gid = blockIdx.x * blockDim.x + threadIdx.x;

    if (gid < N_NODESC) {
        g_cursor[gid] = 0;
        g_flag2[gid] = 0;
        g_flag3[gid] = 0;
    }
    if (gid == 0) { g_nf2 = 0; g_nf3 = 0; }

    {
        float4* ego4 = reinterpret_cast<float4*>(g_ego);
        const int ucount = N_USERS * (EMB / 4);
        float4 v = (gid < ucount) ? ue[gid] : ie[gid - ucount];
        ego4[gid] = v;
        __half2 h0 = __float22half2_rn(make_float2(v.x, v.y));
        __half2 h1 = __float22half2_rn(make_float2(v.z, v.w));
        uint2 p;
        p.x = *reinterpret_cast<unsigned*>(&h0);
        p.y = *reinterpret_cast<unsigned*>(&h1);
        g_egoH[gid] = p;
    }

    if (gid < 3 * BATCHC * 16) {
        int r = gid >> 4;
        int g = gid & 15;
        float4 v;
        if (r < BATCHC) {
            v = ue[users[r] * 16 + g];
        } else if (r < 2 * BATCHC) {
            v = ie[pos[r - BATCHC] * 16 + g];
        } else {
            v = ie[neg[r - 2 * BATCHC] * 16 + g];
        }
        *reinterpret_cast<float4*>(&out[(size_t)r * (4 * EMB) + g * 4]) = v;
    }
}

// ---------------- kernel 2: ELL scatter + mark3 ----------------
__global__ void scatter_kernel(const int* __restrict__ row,
                               const int* __restrict__ col,
                               const float* __restrict__ val,
                               const int* __restrict__ users,
                               const int* __restrict__ pos,
                               const int* __restrict__ neg) {
    int e = blockIdx.x * blockDim.x + threadIdx.x;
    if (e >= N_EDGESC) return;
    int r = row[e];
    int p = atomicAdd(&g_cursor[r], 1);
    if (p < ELLW)
        g_cedge[r * ELLW + p] = make_int2(col[e], __float_as_int(val[e]));

    if (e < 3 * BATCHC) {
        int n;
        if (e < BATCHC) n = users[e];
        else if (e < 2 * BATCHC) n = N_USERS + pos[e - BATCHC];
        else n = N_USERS + neg[e - 2 * BATCHC];
        if (atomicExch(&g_flag3[n], 1) == 0) {
            int q = atomicAdd(&g_nf3, 1);
            g_list3[q] = n;
        }
        if (atomicExch(&g_flag2[n], 1) == 0) {
            int q = atomicAdd(&g_nf2, 1);
            g_list2[q] = n;
        }
    }
}

// ---------------- kernel 3: aggregation, 8 lanes/node ----------------
__global__ void aggregate_kernel(int mode) {
    int gid = blockIdx.x * blockDim.x + threadIdx.x;
    int i = gid >> 3;
    int g = gid & 7;
    int node;
    if (mode == 0) {
        node = i;
        if (node >= N_NODESC) return;
    } else if (mode == 2) {
        if (i >= g_nf2) return;
        node = g_list2[i];
    } else {
        if (i >= g_nf3) return;
        node = g_list3[i];
    }
    const uint4* egoH4 = reinterpret_cast<const uint4*>(g_egoH);

    int cnt = min(g_cursor[node], ELLW);
    int beg = node * ELLW;
    int end = beg + cnt;
    float a0 = 0.f, a1 = 0.f, a2 = 0.f, a3 = 0.f;
    float a4 = 0.f, a5 = 0.f, a6 = 0.f, a7 = 0.f;
#pragma unroll 4
    for (int e = beg; e < end; e++) {
        int2 ev = g_cedge[e];
        float v = __int_as_float(ev.y);
        uint4 p = egoH4[ev.x * 8 + g];
        float2 f0 = __half22float2(*reinterpret_cast<__half2*>(&p.x));
        float2 f1 = __half22float2(*reinterpret_cast<__half2*>(&p.y));
        float2 f2 = __half22float2(*reinterpret_cast<__half2*>(&p.z));
        float2 f3 = __half22float2(*reinterpret_cast<__half2*>(&p.w));
        a0 += v * f0.x; a1 += v * f0.y;
        a2 += v * f1.x; a3 += v * f1.y;
        a4 += v * f2.x; a5 += v * f2.y;
        a6 += v * f3.x; a7 += v * f3.y;
    }
    float* nr = g_neigh + node * EMB + g * 8;
    *reinterpret_cast<float4*>(nr)     = make_float4(a0, a1, a2, a3);
    *reinterpret_cast<float4*>(nr + 4) = make_float4(a4, a5, a6, a7);
}

// ---------------- frontier propagate ----------------
__global__ void propagate_kernel() {
    int gid = blockIdx.x * blockDim.x + threadIdx.x;
    int i = gid >> 4;
    int lane = gid & 15;
    if (i >= g_nf3) return;
    int n = g_list3[i];
    int beg = n * ELLW;
    int end = beg + min(g_cursor[n], ELLW);
    for (int e = beg + lane; e < end; e += 16) {
        int c = g_cedge[e].x;
        if (atomicExch(&g_flag2[c], 1) == 0) {
            int p = atomicAdd(&g_nf2, 1);
            g_list2[p] = c;
        }
    }
}

// ---------------- transform v4: HMMA tensor-core GEMM ----------------
// D[128,64] = X[128,128]h @ W[128,64]h + bias; X cols (2k,2k+1)=(neigh_k, ego_k*neigh_k),
// W rows (2k,2k+1)=(Wgc[k], Wbi[k]). Swizzle: 16B chunk index ^= (row & 7).
__global__ void __launch_bounds__(TTHREADS)
transform_kernel(const float* __restrict__ Wgc,
                 const float* __restrict__ bgc,
                 const float* __restrict__ Wbi,
                 const float* __restrict__ bbi,
                 int layer, int mode) {
    extern __shared__ char dsm[];
    char* sX = dsm + SX_OFF;
    char* sW = dsm + SW_OFF;
    float* sb = reinterpret_cast<float*>(dsm + SB_OFF);
    int* sNode = reinterpret_cast<int*>(dsm + SN_OFF);

    const int tid = threadIdx.x;
    const int base = blockIdx.x * TN;

    if (tid < TN) {
        int idx = base + tid;
        int node = -1;
        if (mode == 0) {
            if (idx < N_NODESC) node = idx;
        } else if (mode == 2) {
            if (idx < g_nf2) node = g_list2[idx];
        } else {
            if (idx < g_nf3) node = g_list3[idx];
        }
        sNode[tid] = node;
    }

    // stage W fp16 (interleaved gc/bi rows), swizzled 16B chunks
    {
        const float* w1g = Wgc + layer * EMB * EMB;
        const float* w2g = Wbi + layer * EMB * EMB;
        for (int i = tid; i < 128 * 8; i += TTHREADS) {   // (row, chunk)
            int r = i >> 3, c = i & 7;
            int k = r >> 1;
            const float* src = (r & 1) ? (w2g + k * EMB + c * 8) : (w1g + k * EMB + c * 8);
            __half2 h0 = __float22half2_rn(make_float2(src[0], src[1]));
            __half2 h1 = __float22half2_rn(make_float2(src[2], src[3]));
            __half2 h2 = __float22half2_rn(make_float2(src[4], src[5]));
            __half2 h3 = __float22half2_rn(make_float2(src[6], src[7]));
            uint4 hp;
            hp.x = *reinterpret_cast<unsigned*>(&h0);
            hp.y = *reinterpret_cast<unsigned*>(&h1);
            hp.z = *reinterpret_cast<unsigned*>(&h2);
            hp.w = *reinterpret_cast<unsigned*>(&h3);
            *reinterpret_cast<uint4*>(sW + r * 128 + ((c ^ (r & 7)) << 4)) = hp;
        }
        if (tid < EMB)
            sb[tid] = bgc[layer * EMB + tid] + bbi[layer * EMB + tid];
    }
    __syncthreads();

    // stage X fp16: per (local node, kq): chunk kq holds cols 8kq..8kq+7
    {
        const float4* ego4 = reinterpret_cast<const float4*>(g_ego);
        const float4* neigh4 = reinterpret_cast<const float4*>(g_neigh);
        for (int i = tid; i < TN * 16; i += TTHREADS) {
            int local = i >> 4;
            int kq = i & 15;
            int gn = sNode[local];
            uint4 hp = make_uint4(0, 0, 0, 0);
            if (gn >= 0) {
                float4 n = neigh4[gn * 16 + kq];
                float4 e = ego4[gn * 16 + kq];
                __half2 h0 = __float22half2_rn(make_float2(n.x, e.x * n.x));
                __half2 h1 = __float22half2_rn(make_float2(n.y, e.y * n.y));
                __half2 h2 = __float22half2_rn(make_float2(n.z, e.z * n.z));
                __half2 h3 = __float22half2_rn(make_float2(n.w, e.w * n.w));
                hp.x = *reinterpret_cast<unsigned*>(&h0);
                hp.y = *reinterpret_cast<unsigned*>(&h1);
                hp.z = *reinterpret_cast<unsigned*>(&h2);
                hp.w = *reinterpret_cast<unsigned*>(&h3);
            }
            *reinterpret_cast<uint4*>(sX + local * 256 + ((kq ^ (local & 7)) << 4)) = hp;
        }
    }
    __syncthreads();

    const int w = tid >> 5;    // warp 0..7 -> nodes w*16..w*16+15
    const int l = tid & 31;

    // accumulators: 8 n-tiles x 4 (c-frag), init with bias
    float acc[8][4];
#pragma unroll
    for (int nt = 0; nt < 8; nt++) {
        float b0 = sb[nt * 8 + 2 * (l & 3)];
        float b1 = sb[nt * 8 + 2 * (l & 3) + 1];
        acc[nt][0] = b0; acc[nt][1] = b1; acc[nt][2] = b0; acc[nt][3] = b1;
    }

    // A ldmatrix address (this lane), per kk
    int rowA = w * 16 + (l & 7) + ((l >> 3) & 1) * 8;
    int khalf = (l >> 4) & 1;
    unsigned baseX = (unsigned)__cvta_generic_to_shared(sX);
    unsigned baseW = (unsigned)__cvta_generic_to_shared(sW);
    // B ldmatrix row (lanes 0-15 matter; clamp others to valid dup)
    int lB = l & 15;

#pragma unroll
    for (int kk = 0; kk < 8; kk++) {
        int chunkA = kk * 2 + khalf;
        unsigned addrA = baseX + rowA * 256 + (((chunkA ^ (rowA & 7))) << 4);
        unsigned a0, a1, a2, a3;
        asm volatile("ldmatrix.sync.aligned.m8n8.x4.shared.b16 {%0,%1,%2,%3}, [%4];"
                     : "=r"(a0), "=r"(a1), "=r"(a2), "=r"(a3) : "r"(addrA));

        int rowW = kk * 16 + lB;
        unsigned rowWoff = baseW + rowW * 128;
        int rsw = rowW & 7;
#pragma unroll
        for (int nt = 0; nt < 8; nt++) {
            unsigned addrB = rowWoff + (((nt ^ rsw)) << 4);
            unsigned b0, b1;
            asm volatile("ldmatrix.sync.aligned.m8n8.x2.trans.shared.b16 {%0,%1}, [%2];"
                         : "=r"(b0), "=r"(b1) : "r"(addrB));
            asm volatile(
                "mma.sync.aligned.m16n8k16.row.col.f32.f16.f16.f32 "
                "{%0,%1,%2,%3}, {%4,%5,%6,%7}, {%8,%9}, {%0,%1,%2,%3};"
                : "+f"(acc[nt][0]), "+f"(acc[nt][1]), "+f"(acc[nt][2]), "+f"(acc[nt][3])
                : "r"(a0), "r"(a1), "r"(a2), "r"(a3), "r"(b0), "r"(b1));
        }
    }

    // epilogue: leaky, quad-shuffle l2-norm (rows l>>2 and l>>2+8), store fp32 + fp16
    float sA = 0.f, sB = 0.f;
#pragma unroll
    for (int nt = 0; nt < 8; nt++) {
        float v0 = acc[nt][0]; v0 = (v0 >= 0.f) ? v0 : NEG_SLOPE * v0;
        float v1 = acc[nt][1]; v1 = (v1 >= 0.f) ? v1 : NEG_SLOPE * v1;
        float v2 = acc[nt][2]; v2 = (v2 >= 0.f) ? v2 : NEG_SLOPE * v2;
        float v3 = acc[nt][3]; v3 = (v3 >= 0.f) ? v3 : NEG_SLOPE * v3;
        acc[nt][0] = v0; acc[nt][1] = v1; acc[nt][2] = v2; acc[nt][3] = v3;
        sA += v0 * v0 + v1 * v1;
        sB += v2 * v2 + v3 * v3;
    }
    const unsigned mask = 0xffffffffu;
    sA += __shfl_xor_sync(mask, sA, 1);
    sA += __shfl_xor_sync(mask, sA, 2);
    sB += __shfl_xor_sync(mask, sB, 1);
    sB += __shfl_xor_sync(mask, sB, 2);
    float scA = 1.0f / fmaxf(sqrtf(sA), 1e-12f);
    float scB = 1.0f / fmaxf(sqrtf(sB), 1e-12f);

    int localA = w * 16 + (l >> 2);
    int localB = localA + 8;
    int gnA = sNode[localA];
    int gnB = sNode[localB];
    int colb = 2 * (l & 3);
    __half* egoHh = reinterpret_cast<__half*>(g_egoH);

#pragma unroll
    for (int nt = 0; nt < 8; nt++) {
        int col = nt * 8 + colb;
        if (gnA >= 0) {
            float v0 = acc[nt][0] * scA;
            float v1 = acc[nt][1] * scA;
            *reinterpret_cast<float2*>(g_ego + gnA * EMB + col) = make_float2(v0, v1);
            __half2 h = __float22half2_rn(make_float2(v0, v1));
            *reinterpret_cast<unsigned*>(egoHh + gnA * EMB + col) =
                *reinterpret_cast<unsigned*>(&h);
        }
        if (gnB >= 0) {
            float v2 = acc[nt][2] * scB;
            float v3 = acc[nt][3] * scB;
            *reinterpret_cast<float2*>(g_ego + gnB * EMB + col) = make_float2(v2, v3);
            __half2 h = __float22half2_rn(make_float2(v2, v3));
            *reinterpret_cast<unsigned*>(egoHh + gnB * EMB + col) =
                *reinterpret_cast<unsigned*>(&h);
        }
    }
}

// ---------------- output gather ----------------
__global__ void gather_out_kernel(const int* __restrict__ users,
                                  const int* __restrict__ pos,
                                  const int* __restrict__ neg,
                                  float* __restrict__ out,
                                  int stage) {
    int gid = blockIdx.x * blockDim.x + threadIdx.x;
    int r = gid >> 4;
    if (r >= 3 * BATCHC) return;
    int g = gid & 15;
    int node;
    if (r < BATCHC) node = users[r];
    else if (r < 2 * BATCHC) node = N_USERS + pos[r - BATCHC];
    else node = N_USERS + neg[r - 2 * BATCHC];

    const float4* ego4 = reinterpret_cast<const float4*>(g_ego);
    float4 v = ego4[node * 16 + g];
    *reinterpret_cast<float4*>(&out[(size_t)r * (4 * EMB) + stage * EMB + g * 4]) = v;
}

// ---------------- launch ----------------
extern "C" void kernel_launch(void* const* d_in, const int* in_sizes, int n_in,
                              void* d_out, int out_size) {
    const int*   edge_row = (const int*)d_in[0];
    const int*   edge_col = (const int*)d_in[1];
    const float* edge_val = (const float*)d_in[2];
    const float* user_emb = (const float*)d_in[3];
    const float* item_emb = (const float*)d_in[4];
    const float* W_gc     = (const float*)d_in[5];
    const float* b_gc     = (const float*)d_in[6];
    const float* W_bi     = (const float*)d_in[7];
    const float* b_bi     = (const float*)d_in[8];
    const int*   users    = (const int*)d_in[9];
    const int*   pos      = (const int*)d_in[10];
    const int*   neg      = (const int*)d_in[11];
    float* out = (float*)d_out;

    const int T = 256;
    const int nbEdges = (N_EDGESC + T - 1) / T;        // 37500
    const int nbPrep = (N_NODESC * 16) / T;            // 18750
    const int nbNode8 = (N_NODESC * 8) / T;            // 9375
    const int nbGather = (3 * BATCHC * 16 + T - 1) / T;
    const int nbTrans = (N_NODESC + TN - 1) / TN;      // 2344
    const int nbProp = (3 * BATCHC * 16 + T - 1) / T;  // 768
    const int nbAgg3 = (3 * BATCHC * 8 + T - 1) / T;   // 384
    const int nbTrans3 = (3 * BATCHC + TN - 1) / TN;   // 96

    cudaFuncSetAttribute(transform_kernel, cudaFuncAttributeMaxDynamicSharedMemorySize,
                         SMEM_TOTAL);

    // 1: prep = zero + copy ego + stage-0 output
    prep_kernel<<<nbPrep, T>>>((const float4*)user_emb, (const float4*)item_emb,
                               users, pos, neg, out);
    // 2: ELL scatter + mark3
    scatter_kernel<<<nbEdges, T>>>(edge_row, edge_col, edge_val, users, pos, neg);
    // 3: layer-1 aggregate
    aggregate_kernel<<<nbNode8, T>>>(0);
    // 4: layer-1 transform (HMMA)  <-- ncu profiled slot (A/B vs round 14)
    transform_kernel<<<nbTrans, TTHREADS, SMEM_TOTAL>>>(W_gc, b_gc, W_bi, b_bi, 0, 0);

    propagate_kernel<<<nbProp, T>>>();
    gather_out_kernel<<<nbGather, T>>>(users, pos, neg, out, 1);

    // layer 2: frontier F2
    aggregate_kernel<<<nbNode8, T>>>(2);
    transform_kernel<<<nbTrans, TTHREADS, SMEM_TOTAL>>>(W_gc, b_gc, W_bi, b_bi, 1, 2);
    gather_out_kernel<<<nbGather, T>>>(users, pos, neg, out, 2);

    // layer 3: frontier F3
    aggregate_kernel<<<nbAgg3, T>>>(3);
    transform_kernel<<<nbTrans3, TTHREADS, SMEM_TOTAL>>>(W_gc, b_gc, W_bi, b_bi, 2, 3);
    gather_out_kernel<<<nbGather, T>>>(users, pos, neg, out, 3);
}

// round 17
// speedup vs baseline: 1.6520x; 1.0551x over previous
#include <cuda_runtime.h>
#include <cuda_fp16.h>

#define N_USERS 100000
#define N_ITEMS 200000
#define N_NODESC 300000
#define EMB 64
#define NLAYERS 3
#define N_EDGESC 9600000
#define BATCHC 4096
#define NEG_SLOPE 0.2f

#define TN 128          // nodes per transform block
#define TTHREADS 256    // 8 warps x 16 nodes
#define ELLW 128        // ELL slots per node

// transform smem layout (bytes)
#define SX_OFF 0            // X fp16: 128 rows x 256 B (swizzled chunks)
#define SW_OFF 32768        // W fp16: 128 rows x 128 B (swizzled chunks)
#define SB_OFF 49152        // bias fp32: 64 floats
#define SN_OFF 49408        // node ids: 128 ints
#define SMEM_TOTAL 49920

typedef unsigned long long ull;

// ---------------- device scratch (no mallocs allowed) ----------------
__device__ float g_ego[N_NODESC * EMB];     // fp32 master (write in transform, read by gathers)
__device__ uint2 g_egoH[N_NODESC * 16];     // fp16 ego mirror
__device__ uint2 g_neighH[N_NODESC * 16];   // fp16 neigh (aggregate output)
__device__ int   g_cursor[N_NODESC];
__device__ int2  g_cedge[N_NODESC * ELLW];
// frontier machinery
__device__ int   g_flag2[N_NODESC];
__device__ int   g_flag3[N_NODESC];
__device__ int   g_list2[N_NODESC];
__device__ int   g_list3[3 * BATCHC];
__device__ int   g_nf2;
__device__ int   g_nf3;

// ---------------- kernel 1: prep = zero + copy_ego + stage-0 output ----------------
__global__ void prep_kernel(const float4* __restrict__ ue,
                            const float4* __restrict__ ie,
                            const int* __restrict__ users,
                            const int* __restrict__ pos,
                            const int* __restrict__ neg,
                            float* __restrict__ out) {
    int gid = blockIdx.x * blockDim.x + threadIdx.x;

    if (gid < N_NODESC) {
        g_cursor[gid] = 0;
        g_flag2[gid] = 0;
        g_flag3[gid] = 0;
    }
    if (gid == 0) { g_nf2 = 0; g_nf3 = 0; }

    {
        float4* ego4 = reinterpret_cast<float4*>(g_ego);
        const int ucount = N_USERS * (EMB / 4);
        float4 v = (gid < ucount) ? ue[gid] : ie[gid - ucount];
        ego4[gid] = v;
        __half2 h0 = __float22half2_rn(make_float2(v.x, v.y));
        __half2 h1 = __float22half2_rn(make_float2(v.z, v.w));
        uint2 p;
        p.x = *reinterpret_cast<unsigned*>(&h0);
        p.y = *reinterpret_cast<unsigned*>(&h1);
        g_egoH[gid] = p;
    }

    if (gid < 3 * BATCHC * 16) {
        int r = gid >> 4;
        int g = gid & 15;
        float4 v;
        if (r < BATCHC) {
            v = ue[users[r] * 16 + g];
        } else if (r < 2 * BATCHC) {
            v = ie[pos[r - BATCHC] * 16 + g];
        } else {
            v = ie[neg[r - 2 * BATCHC] * 16 + g];
        }
        *reinterpret_cast<float4*>(&out[(size_t)r * (4 * EMB) + g * 4]) = v;
    }
}

// ---------------- kernel 2: ELL scatter + mark3 ----------------
__global__ void scatter_kernel(const int* __restrict__ row,
                               const int* __restrict__ col,
                               const float* __restrict__ val,
                               const int* __restrict__ users,
                               const int* __restrict__ pos,
                               const int* __restrict__ neg) {
    int e = blockIdx.x * blockDim.x + threadIdx.x;
    if (e >= N_EDGESC) return;
    int r = row[e];
    int p = atomicAdd(&g_cursor[r], 1);
    if (p < ELLW)
        g_cedge[r * ELLW + p] = make_int2(col[e], __float_as_int(val[e]));

    if (e < 3 * BATCHC) {
        int n;
        if (e < BATCHC) n = users[e];
        else if (e < 2 * BATCHC) n = N_USERS + pos[e - BATCHC];
        else n = N_USERS + neg[e - 2 * BATCHC];
        if (atomicExch(&g_flag3[n], 1) == 0) {
            int q = atomicAdd(&g_nf3, 1);
            g_list3[q] = n;
        }
        if (atomicExch(&g_flag2[n], 1) == 0) {
            int q = atomicAdd(&g_nf2, 1);
            g_list2[q] = n;
        }
    }
}

// ---------------- kernel 3: aggregation, 8 lanes/node, fp16 output ----------------
__global__ void aggregate_kernel(int mode) {
    int gid = blockIdx.x * blockDim.x + threadIdx.x;
    int i = gid >> 3;
    int g = gid & 7;
    int node;
    if (mode == 0) {
        node = i;
        if (node >= N_NODESC) return;
    } else if (mode == 2) {
        if (i >= g_nf2) return;
        node = g_list2[i];
    } else {
        if (i >= g_nf3) return;
        node = g_list3[i];
    }
    const uint4* egoH4 = reinterpret_cast<const uint4*>(g_egoH);

    int cnt = min(g_cursor[node], ELLW);
    int beg = node * ELLW;
    int end = beg + cnt;
    float a0 = 0.f, a1 = 0.f, a2 = 0.f, a3 = 0.f;
    float a4 = 0.f, a5 = 0.f, a6 = 0.f, a7 = 0.f;
#pragma unroll 4
    for (int e = beg; e < end; e++) {
        int2 ev = g_cedge[e];
        float v = __int_as_float(ev.y);
        uint4 p = egoH4[ev.x * 8 + g];
        float2 f0 = __half22float2(*reinterpret_cast<__half2*>(&p.x));
        float2 f1 = __half22float2(*reinterpret_cast<__half2*>(&p.y));
        float2 f2 = __half22float2(*reinterpret_cast<__half2*>(&p.z));
        float2 f3 = __half22float2(*reinterpret_cast<__half2*>(&p.w));
        a0 += v * f0.x; a1 += v * f0.y;
        a2 += v * f1.x; a3 += v * f1.y;
        a4 += v * f2.x; a5 += v * f2.y;
        a6 += v * f3.x; a7 += v * f3.y;
    }
    __half2 h0 = __float22half2_rn(make_float2(a0, a1));
    __half2 h1 = __float22half2_rn(make_float2(a2, a3));
    __half2 h2 = __float22half2_rn(make_float2(a4, a5));
    __half2 h3 = __float22half2_rn(make_float2(a6, a7));
    uint4 hp;
    hp.x = *reinterpret_cast<unsigned*>(&h0);
    hp.y = *reinterpret_cast<unsigned*>(&h1);
    hp.z = *reinterpret_cast<unsigned*>(&h2);
    hp.w = *reinterpret_cast<unsigned*>(&h3);
    reinterpret_cast<uint4*>(g_neighH)[node * 8 + g] = hp;
}

// ---------------- frontier propagate ----------------
__global__ void propagate_kernel() {
    int gid = blockIdx.x * blockDim.x + threadIdx.x;
    int i = gid >> 4;
    int lane = gid & 15;
    if (i >= g_nf3) return;
    int n = g_list3[i];
    int beg = n * ELLW;
    int end = beg + min(g_cursor[n], ELLW);
    for (int e = beg + lane; e < end; e += 16) {
        int c = g_cedge[e].x;
        if (atomicExch(&g_flag2[c], 1) == 0) {
            int p = atomicAdd(&g_nf2, 1);
            g_list2[p] = c;
        }
    }
}

// ---------------- transform v5: HMMA GEMM, X staged from fp16 mirrors ----------------
// D[128,64] = X[128,128]h @ W[128,64]h + bias; X cols (2k,2k+1)=(neigh_k, ego_k*neigh_k).
__global__ void __launch_bounds__(TTHREADS)
transform_kernel(const float* __restrict__ Wgc,
                 const float* __restrict__ bgc,
                 const float* __restrict__ Wbi,
                 const float* __restrict__ bbi,
                 int layer, int mode) {
    extern __shared__ char dsm[];
    char* sX = dsm + SX_OFF;
    char* sW = dsm + SW_OFF;
    float* sb = reinterpret_cast<float*>(dsm + SB_OFF);
    int* sNode = reinterpret_cast<int*>(dsm + SN_OFF);

    const int tid = threadIdx.x;
    const int base = blockIdx.x * TN;

    if (tid < TN) {
        int idx = base + tid;
        int node = -1;
        if (mode == 0) {
            if (idx < N_NODESC) node = idx;
        } else if (mode == 2) {
            if (idx < g_nf2) node = g_list2[idx];
        } else {
            if (idx < g_nf3) node = g_list3[idx];
        }
        sNode[tid] = node;
    }

    // stage W fp16 (interleaved gc/bi rows), swizzled 16B chunks
    {
        const float* w1g = Wgc + layer * EMB * EMB;
        const float* w2g = Wbi + layer * EMB * EMB;
        for (int i = tid; i < 128 * 8; i += TTHREADS) {   // (row, chunk)
            int r = i >> 3, c = i & 7;
            int k = r >> 1;
            const float* src = (r & 1) ? (w2g + k * EMB + c * 8) : (w1g + k * EMB + c * 8);
            __half2 h0 = __float22half2_rn(make_float2(src[0], src[1]));
            __half2 h1 = __float22half2_rn(make_float2(src[2], src[3]));
            __half2 h2 = __float22half2_rn(make_float2(src[4], src[5]));
            __half2 h3 = __float22half2_rn(make_float2(src[6], src[7]));
            uint4 hp;
            hp.x = *reinterpret_cast<unsigned*>(&h0);
            hp.y = *reinterpret_cast<unsigned*>(&h1);
            hp.z = *reinterpret_cast<unsigned*>(&h2);
            hp.w = *reinterpret_cast<unsigned*>(&h3);
            *reinterpret_cast<uint4*>(sW + r * 128 + ((c ^ (r & 7)) << 4)) = hp;
        }
        if (tid < EMB)
            sb[tid] = bgc[layer * EMB + tid] + bbi[layer * EMB + tid];
    }
    __syncthreads();

    // stage X fp16 from the fp16 mirrors: chunk kq holds cols 8kq..8kq+7
    {
        for (int i = tid; i < TN * 16; i += TTHREADS) {
            int local = i >> 4;
            int kq = i & 15;
            int gn = sNode[local];
            uint4 hp = make_uint4(0, 0, 0, 0);
            if (gn >= 0) {
                uint2 nh = g_neighH[gn * 16 + kq];
                uint2 eh = g_egoH[gn * 16 + kq];
                float2 n01 = __half22float2(*reinterpret_cast<__half2*>(&nh.x));
                float2 n23 = __half22float2(*reinterpret_cast<__half2*>(&nh.y));
                float2 e01 = __half22float2(*reinterpret_cast<__half2*>(&eh.x));
                float2 e23 = __half22float2(*reinterpret_cast<__half2*>(&eh.y));
                __half2 h0 = __float22half2_rn(make_float2(n01.x, e01.x * n01.x));
                __half2 h1 = __float22half2_rn(make_float2(n01.y, e01.y * n01.y));
                __half2 h2 = __float22half2_rn(make_float2(n23.x, e23.x * n23.x));
                __half2 h3 = __float22half2_rn(make_float2(n23.y, e23.y * n23.y));
                hp.x = *reinterpret_cast<unsigned*>(&h0);
                hp.y = *reinterpret_cast<unsigned*>(&h1);
                hp.z = *reinterpret_cast<unsigned*>(&h2);
                hp.w = *reinterpret_cast<unsigned*>(&h3);
            }
            *reinterpret_cast<uint4*>(sX + local * 256 + ((kq ^ (local & 7)) << 4)) = hp;
        }
    }
    __syncthreads();

    const int w = tid >> 5;    // warp 0..7 -> nodes w*16..w*16+15
    const int l = tid & 31;

    // accumulators: 8 n-tiles x 4 (c-frag), init with bias
    float acc[8][4];
#pragma unroll
    for (int nt = 0; nt < 8; nt++) {
        float b0 = sb[nt * 8 + 2 * (l & 3)];
        float b1 = sb[nt * 8 + 2 * (l & 3) + 1];
        acc[nt][0] = b0; acc[nt][1] = b1; acc[nt][2] = b0; acc[nt][3] = b1;
    }

    int rowA = w * 16 + (l & 7) + ((l >> 3) & 1) * 8;
    int khalf = (l >> 4) & 1;
    unsigned baseX = (unsigned)__cvta_generic_to_shared(sX);
    unsigned baseW = (unsigned)__cvta_generic_to_shared(sW);
    int lB = l & 15;

#pragma unroll
    for (int kk = 0; kk < 8; kk++) {
        int chunkA = kk * 2 + khalf;
        unsigned addrA = baseX + rowA * 256 + (((chunkA ^ (rowA & 7))) << 4);
        unsigned a0, a1, a2, a3;
        asm volatile("ldmatrix.sync.aligned.m8n8.x4.shared.b16 {%0,%1,%2,%3}, [%4];"
                     : "=r"(a0), "=r"(a1), "=r"(a2), "=r"(a3) : "r"(addrA));

        int rowW = kk * 16 + lB;
        unsigned rowWoff = baseW + rowW * 128;
        int rsw = rowW & 7;
#pragma unroll
        for (int nt = 0; nt < 8; nt++) {
            unsigned addrB = rowWoff + (((nt ^ rsw)) << 4);
            unsigned b0, b1;
            asm volatile("ldmatrix.sync.aligned.m8n8.x2.trans.shared.b16 {%0,%1}, [%2];"
                         : "=r"(b0), "=r"(b1) : "r"(addrB));
            asm volatile(
                "mma.sync.aligned.m16n8k16.row.col.f32.f16.f16.f32 "
                "{%0,%1,%2,%3}, {%4,%5,%6,%7}, {%8,%9}, {%0,%1,%2,%3};"
                : "+f"(acc[nt][0]), "+f"(acc[nt][1]), "+f"(acc[nt][2]), "+f"(acc[nt][3])
                : "r"(a0), "r"(a1), "r"(a2), "r"(a3), "r"(b0), "r"(b1));
        }
    }

    // epilogue: leaky, quad-shuffle l2-norm, store fp32 + fp16
    float sA = 0.f, sB = 0.f;
#pragma unroll
    for (int nt = 0; nt < 8; nt++) {
        float v0 = acc[nt][0]; v0 = (v0 >= 0.f) ? v0 : NEG_SLOPE * v0;
        float v1 = acc[nt][1]; v1 = (v1 >= 0.f) ? v1 : NEG_SLOPE * v1;
        float v2 = acc[nt][2]; v2 = (v2 >= 0.f) ? v2 : NEG_SLOPE * v2;
        float v3 = acc[nt][3]; v3 = (v3 >= 0.f) ? v3 : NEG_SLOPE * v3;
        acc[nt][0] = v0; acc[nt][1] = v1; acc[nt][2] = v2; acc[nt][3] = v3;
        sA += v0 * v0 + v1 * v1;
        sB += v2 * v2 + v3 * v3;
    }
    const unsigned mask = 0xffffffffu;
    sA += __shfl_xor_sync(mask, sA, 1);
    sA += __shfl_xor_sync(mask, sA, 2);
    sB += __shfl_xor_sync(mask, sB, 1);
    sB += __shfl_xor_sync(mask, sB, 2);
    float scA = 1.0f / fmaxf(sqrtf(sA), 1e-12f);
    float scB = 1.0f / fmaxf(sqrtf(sB), 1e-12f);

    int localA = w * 16 + (l >> 2);
    int localB = localA + 8;
    int gnA = sNode[localA];
    int gnB = sNode[localB];
    int colb = 2 * (l & 3);
    __half* egoHh = reinterpret_cast<__half*>(g_egoH);

#pragma unroll
    for (int nt = 0; nt < 8; nt++) {
        int col = nt * 8 + colb;
        if (gnA >= 0) {
            float v0 = acc[nt][0] * scA;
            float v1 = acc[nt][1] * scA;
            *reinterpret_cast<float2*>(g_ego + gnA * EMB + col) = make_float2(v0, v1);
            __half2 h = __float22half2_rn(make_float2(v0, v1));
            *reinterpret_cast<unsigned*>(egoHh + gnA * EMB + col) =
                *reinterpret_cast<unsigned*>(&h);
        }
        if (gnB >= 0) {
            float v2 = acc[nt][2] * scB;
            float v3 = acc[nt][3] * scB;
            *reinterpret_cast<float2*>(g_ego + gnB * EMB + col) = make_float2(v2, v3);
            __half2 h = __float22half2_rn(make_float2(v2, v3));
            *reinterpret_cast<unsigned*>(egoHh + gnB * EMB + col) =
                *reinterpret_cast<unsigned*>(&h);
        }
    }
}

// ---------------- output gather ----------------
__global__ void gather_out_kernel(const int* __restrict__ users,
                                  const int* __restrict__ pos,
                                  const int* __restrict__ neg,
                                  float* __restrict__ out,
                                  int stage) {
    int gid = blockIdx.x * blockDim.x + threadIdx.x;
    int r = gid >> 4;
    if (r >= 3 * BATCHC) return;
    int g = gid & 15;
    int node;
    if (r < BATCHC) node = users[r];
    else if (r < 2 * BATCHC) node = N_USERS + pos[r - BATCHC];
    else node = N_USERS + neg[r - 2 * BATCHC];

    const float4* ego4 = reinterpret_cast<const float4*>(g_ego);
    float4 v = ego4[node * 16 + g];
    *reinterpret_cast<float4*>(&out[(size_t)r * (4 * EMB) + stage * EMB + g * 4]) = v;
}

// ---------------- launch ----------------
extern "C" void kernel_launch(void* const* d_in, const int* in_sizes, int n_in,
                              void* d_out, int out_size) {
    const int*   edge_row = (const int*)d_in[0];
    const int*   edge_col = (const int*)d_in[1];
    const float* edge_val = (const float*)d_in[2];
    const float* user_emb = (const float*)d_in[3];
    const float* item_emb = (const float*)d_in[4];
    const float* W_gc     = (const float*)d_in[5];
    const float* b_gc     = (const float*)d_in[6];
    const float* W_bi     = (const float*)d_in[7];
    const float* b_bi     = (const float*)d_in[8];
    const int*   users    = (const int*)d_in[9];
    const int*   pos      = (const int*)d_in[10];
    const int*   neg      = (const int*)d_in[11];
    float* out = (float*)d_out;

    const int T = 256;
    const int nbEdges = (N_EDGESC + T - 1) / T;        // 37500
    const int nbPrep = (N_NODESC * 16) / T;            // 18750
    const int nbNode8 = (N_NODESC * 8) / T;            // 9375
    const int nbGather = (3 * BATCHC * 16 + T - 1) / T;
    const int nbTrans = (N_NODESC + TN - 1) / TN;      // 2344
    const int nbProp = (3 * BATCHC * 16 + T - 1) / T;  // 768
    const int nbAgg3 = (3 * BATCHC * 8 + T - 1) / T;   // 384
    const int nbTrans3 = (3 * BATCHC + TN - 1) / TN;   // 96

    cudaFuncSetAttribute(transform_kernel, cudaFuncAttributeMaxDynamicSharedMemorySize,
                         SMEM_TOTAL);

    // 1: prep = zero + copy ego + stage-0 output
    prep_kernel<<<nbPrep, T>>>((const float4*)user_emb, (const float4*)item_emb,
                               users, pos, neg, out);
    // 2: ELL scatter + mark3
    scatter_kernel<<<nbEdges, T>>>(edge_row, edge_col, edge_val, users, pos, neg);
    // 3: layer-1 aggregate (fp16 output)
    aggregate_kernel<<<nbNode8, T>>>(0);
    // 4: layer-1 transform (HMMA, fp16 inputs)  <-- ncu profiled slot (A/B vs round 15)
    transform_kernel<<<nbTrans, TTHREADS, SMEM_TOTAL>>>(W_gc, b_gc, W_bi, b_bi, 0, 0);

    propagate_kernel<<<nbProp, T>>>();
    gather_out_kernel<<<nbGather, T>>>(users, pos, neg, out, 1);

    // layer 2: frontier F2
    aggregate_kernel<<<nbNode8, T>>>(2);
    transform_kernel<<<nbTrans, TTHREADS, SMEM_TOTAL>>>(W_gc, b_gc, W_bi, b_bi, 1, 2);
    gather_out_kernel<<<nbGather, T>>>(users, pos, neg, out, 2);

    // layer 3: frontier F3
    aggregate_kernel<<<nbAgg3, T>>>(3);
    transform_kernel<<<nbTrans3, TTHREADS, SMEM_TOTAL>>>(W_gc, b_gc, W_bi, b_bi, 2, 3);
    gather_out_kernel<<<nbGather, T>>>(users, pos, neg, out, 3);
}